// round 12
// baseline (speedup 1.0000x reference)
#include <cuda_runtime.h>
#include <cuda_bf16.h>
#include <cstdint>

// OccupancyGridForestAS: 4.19M points, 8x8x8 block lookup -> 64 trees of 64^3 voxels.
//
// inputs (metadata order):
//   d_in[0]: pts            float32 [N_PTS, 3]
//   d_in[1]: occ_val_grid   float32 [64, 64, 64, 64]
//   d_in[2]: block_lookup   int32   [8, 8, 8]
// output: float32 [N_PTS]
//
// R12: barrier-free per-thread cp.async self-staging. Each thread double-
// buffers ITS OWN next 4-point chunk (3x16B cp.async.cg, evict_first policy)
// into private smem slots and reads back only its own data -> no __syncthreads
// in the loop (cp.async groups are per-thread). The stream-load latency moves
// off the register scoreboard; the only remaining exposed wait is the gather.
// Body/policy otherwise = champion R8 (4 pts/iter, smem lut, clamp-free vox,
// __ldcg gather, __stcs out), grid = nsm*8 persistent.

#define RES   64
#define LDIM  8
#define NTHREADS 256

__device__ __forceinline__ uint32_t smem_u32(const void* p) {
    return (uint32_t)__cvta_generic_to_shared(p);
}

__device__ __forceinline__ void cp16(void* s, const void* g, uint64_t pol) {
    asm volatile("cp.async.cg.shared.global.L2::cache_hint [%0], [%1], 16, %2;\n"
                 :: "r"(smem_u32(s)), "l"(g), "l"(pol));
}

__global__ void __launch_bounds__(NTHREADS)
occ_forest_kernel(const float4* __restrict__ pts4,
                  const float*  __restrict__ occ,
                  const int*    __restrict__ lut,
                  float4*       __restrict__ out4,
                  int nc)                      // number of 4-point chunks
{
    __shared__ __align__(16) float4 s_a[2][NTHREADS];   // 8KB
    __shared__ __align__(16) float4 s_b[2][NTHREADS];   // 8KB
    __shared__ __align__(16) float4 s_c[2][NTHREADS];   // 8KB
    __shared__ int s_lut[LDIM * LDIM * LDIM];           // 2KB

    const int tid = threadIdx.x;
    s_lut[tid]       = lut[tid];
    s_lut[tid + 256] = lut[tid + 256];
    __syncthreads();   // only barrier in the kernel (lut visibility)

    uint64_t pol;
    asm("createpolicy.fractional.L2::evict_first.b64 %0, 1.0;" : "=l"(pol));

    const int stride = gridDim.x * blockDim.x;
    int t = blockIdx.x * blockDim.x + tid;
    if (t >= nc) return;

    // Prologue: stage chunk t into stage 0 (this thread's private slots)
    {
        const float4* g = &pts4[3 * t];
        cp16(&s_a[0][tid], g + 0, pol);
        cp16(&s_b[0][tid], g + 1, pol);
        cp16(&s_c[0][tid], g + 2, pol);
        asm volatile("cp.async.commit_group;\n");
    }

    int st = 0;
    for (; t < nc; t += stride) {
        // Issue next chunk's staging (clamped when past the end; harmless
        // re-read, avoids predication)
        {
            int tn  = t + stride;
            int tnc = (tn < nc) ? tn : t;
            const float4* g = &pts4[3 * tnc];
            cp16(&s_a[st ^ 1][tid], g + 0, pol);
            cp16(&s_b[st ^ 1][tid], g + 1, pol);
            cp16(&s_c[st ^ 1][tid], g + 2, pol);
            asm volatile("cp.async.commit_group;\n");
        }
        // Leave the just-issued group in flight; current stage is complete.
        asm volatile("cp.async.wait_group 1;\n");

        // Conflict-free LDS.128 (consecutive float4 across the warp)
        float4 a = s_a[st][tid];
        float4 b = s_b[st][tid];
        float4 c = s_c[st][tid];

        float px[4] = {a.x, a.w, b.z, c.y};
        float py[4] = {a.y, b.x, b.w, c.z};
        float pz[4] = {a.z, b.y, c.x, c.w};

        int  idx[4];
        bool valid[4];

        // Phase 1: index math for all 4 points
#pragma unroll
        for (int i = 0; i < 4; i++) {
            float x = px[i], y = py[i], z = pz[i];

            int bx = (int)floorf(x);
            int by = (int)floorf(y);
            int bz = (int)floorf(z);

            bool in_dom = (bx >= 0) & (bx < LDIM) &
                          (by >= 0) & (by < LDIM) &
                          (bz >= 0) & (bz < LDIM);

            int cx = min(max(bx, 0), LDIM - 1);
            int cy = min(max(by, 0), LDIM - 1);
            int cz = min(max(bz, 0), LDIM - 1);

            int bidx = s_lut[cx * (LDIM * LDIM) + cy * LDIM + cz];
            valid[i] = in_dom && (bidx >= 0);

            // Bit-exact reference float sequence:
            //   block_x = 2*(p - bcs) - 1 ; vox = floor((block_x*0.5+0.5)*RES)
            // valid => x-cx in [0,1) => vox in [0,63]; clamps elided.
            float bxf = 2.0f * (x - (float)cx) - 1.0f;
            float byf = 2.0f * (y - (float)cy) - 1.0f;
            float bzf = 2.0f * (z - (float)cz) - 1.0f;

            int vx = (int)floorf((bxf * 0.5f + 0.5f) * (float)RES);
            int vy = (int)floorf((byf * 0.5f + 0.5f) * (float)RES);
            int vz = (int)floorf((bzf * 0.5f + 0.5f) * (float)RES);

            idx[i] = bidx * (RES * RES * RES) + vx * (RES * RES) + vy * RES + vz;
        }

        // Phase 2: 4 independent predicated gathers (L2-only path) —
        // the only remaining scoreboard wait in the loop.
        float r[4];
#pragma unroll
        for (int i = 0; i < 4; i++)
            r[i] = valid[i] ? __ldcg(&occ[idx[i]]) : 0.0f;

        float4 o;
        o.x = r[0]; o.y = r[1]; o.z = r[2]; o.w = r[3];
        __stcs(&out4[t], o);

        st ^= 1;
    }
}

extern "C" void kernel_launch(void* const* d_in, const int* in_sizes, int n_in,
                              void* d_out, int out_size)
{
    const float4* pts4 = (const float4*)d_in[0];
    const float*  occ  = (const float*)d_in[1];
    const int*    lut  = (const int*)d_in[2];
    float4*       out  = (float4*)d_out;

    int n_pts = in_sizes[0] / 3;       // 4,194,304
    int nc    = n_pts / 4;             // 1,048,576 4-point chunks

    int dev = 0, nsm = 152;
    cudaGetDevice(&dev);
    cudaDeviceGetAttribute(&nsm, cudaDevAttrMultiProcessorCount, dev);

    int blocks = nsm * 8;              // persistent, 8 blocks/SM
    occ_forest_kernel<<<blocks, NTHREADS>>>(pts4, occ, lut, out, nc);
}

// round 13
// speedup vs baseline: 1.5736x; 1.5736x over previous
#include <cuda_runtime.h>
#include <cuda_bf16.h>

// OccupancyGridForestAS: 4.19M points, 8x8x8 block lookup -> 64 trees of 64^3 voxels.
//
// inputs (metadata order):
//   d_in[0]: pts            float32 [N_PTS, 3]
//   d_in[1]: occ_val_grid   float32 [64, 64, 64, 64]
//   d_in[2]: block_lookup   int32   [8, 8, 8]
// output: float32 [N_PTS]
//
// R13: champion R8 body (4 pts/iter, 32 regs, flat loop, no barriers),
// launch geometry fixed for exact work quantization: 2048 blocks x 256 thr
// x 2 iterations = 1,048,576 chunks exactly (R8's 1184 blocks gave 3.46
// iters/thread -> 46% of threads ran a 4th iteration into a draining
// machine). 2048 > 1216 resident blocks also gives the HW scheduler a
// work-stealing pool that smooths per-SM finish-time variance.
// Cache policy: __ldcs stream / __ldcg gather / __stcs out (proven).

#define RES   64
#define LDIM  8
#define NTHREADS 256
#define NBLOCKS  2048

__global__ void __launch_bounds__(NTHREADS)
occ_forest_kernel(const float4* __restrict__ pts4,
                  const float*  __restrict__ occ,
                  const int*    __restrict__ lut,
                  float4*       __restrict__ out4,
                  int nc)                      // number of 4-point chunks
{
    __shared__ int s_lut[LDIM * LDIM * LDIM];  // 512 ints = 2KB
    {
        int tid = threadIdx.x;
        s_lut[tid]       = lut[tid];
        s_lut[tid + 256] = lut[tid + 256];
    }
    __syncthreads();

    const int stride = gridDim.x * blockDim.x;

#pragma unroll 1
    for (int t = blockIdx.x * blockDim.x + threadIdx.x; t < nc; t += stride) {
        // 4 points = 12 floats = 3 float4 (coalesced, evict-first in L2)
        float4 a = __ldcs(&pts4[3 * t + 0]);
        float4 b = __ldcs(&pts4[3 * t + 1]);
        float4 c = __ldcs(&pts4[3 * t + 2]);

        float px[4] = {a.x, a.w, b.z, c.y};
        float py[4] = {a.y, b.x, b.w, c.z};
        float pz[4] = {a.z, b.y, c.x, c.w};

        int  idx[4];
        bool valid[4];

        // Phase 1: index math for all 4 points (no cross-point dependencies)
#pragma unroll
        for (int i = 0; i < 4; i++) {
            float x = px[i], y = py[i], z = pz[i];

            int bx = (int)floorf(x);
            int by = (int)floorf(y);
            int bz = (int)floorf(z);

            bool in_dom = (bx >= 0) & (bx < LDIM) &
                          (by >= 0) & (by < LDIM) &
                          (bz >= 0) & (bz < LDIM);

            int cx = min(max(bx, 0), LDIM - 1);
            int cy = min(max(by, 0), LDIM - 1);
            int cz = min(max(bz, 0), LDIM - 1);

            int bidx = s_lut[cx * (LDIM * LDIM) + cy * LDIM + cz];
            valid[i] = in_dom && (bidx >= 0);

            // Bit-exact reference float sequence:
            //   block_x = 2*(p - bcs) - 1 ; vox = floor((block_x*0.5+0.5)*RES)
            // valid => x-cx in [0,1) => vox in [0,63]; clamps elided
            // (invalid points never issue the load).
            float bxf = 2.0f * (x - (float)cx) - 1.0f;
            float byf = 2.0f * (y - (float)cy) - 1.0f;
            float bzf = 2.0f * (z - (float)cz) - 1.0f;

            int vx = (int)floorf((bxf * 0.5f + 0.5f) * (float)RES);
            int vy = (int)floorf((byf * 0.5f + 0.5f) * (float)RES);
            int vz = (int)floorf((bzf * 0.5f + 0.5f) * (float)RES);

            idx[i] = bidx * (RES * RES * RES) + vx * (RES * RES) + vy * RES + vz;
        }

        // Phase 2: 4 independent predicated gathers (L2-only path)
        float r[4];
#pragma unroll
        for (int i = 0; i < 4; i++)
            r[i] = valid[i] ? __ldcg(&occ[idx[i]]) : 0.0f;

        float4 o;
        o.x = r[0]; o.y = r[1]; o.z = r[2]; o.w = r[3];
        __stcs(&out4[t], o);
    }
}

extern "C" void kernel_launch(void* const* d_in, const int* in_sizes, int n_in,
                              void* d_out, int out_size)
{
    const float4* pts4 = (const float4*)d_in[0];
    const float*  occ  = (const float*)d_in[1];
    const int*    lut  = (const int*)d_in[2];
    float4*       out  = (float4*)d_out;

    int n_pts = in_sizes[0] / 3;       // 4,194,304
    int nc    = n_pts / 4;             // 1,048,576 4-point chunks

    // 2048 blocks x 256 threads x 2 iterations == nc exactly.
    occ_forest_kernel<<<NBLOCKS, NTHREADS>>>(pts4, occ, lut, out, nc);
}